// round 1
// baseline (speedup 1.0000x reference)
#include <cuda_runtime.h>
#include <math.h>

#define Bb 32
#define Nn 64
#define Dd 256
#define PEN 10000.0f
#define INV_TEMP 20.0f   // 1/0.05

// ---------------- device scratch (no allocations allowed) ----------------
__device__ float g_A [Bb*Nn*Dd];   // s_t  @ W1a         (2 MB)
__device__ float g_Bm[Bb*Nn*Dd];   // s_t1 @ W1b         (2 MB)
__device__ float g_la[Bb*Nn*Nn];   // log_alpha          (512 KB)

__device__ __forceinline__ float clip50(float x){ return fminf(fmaxf(x, -50.f), 50.f); }

__device__ __forceinline__ unsigned long long pack2(float x, float y){
    unsigned long long r;
    asm("mov.b64 %0, {%1, %2};" : "=l"(r) : "f"(x), "f"(y));
    return r;
}
__device__ __forceinline__ void unpack2(unsigned long long v, float &lo, float &hi){
    asm("mov.b64 {%0, %1}, %2;" : "=f"(lo), "=f"(hi) : "l"(v));
}
__device__ __forceinline__ void fma2(unsigned long long &acc, unsigned long long a, unsigned long long b){
    asm("fma.rn.f32x2 %0, %1, %2, %0;" : "+l"(acc) : "l"(a), "l"(b));
}
__device__ __forceinline__ unsigned long long fma2r(unsigned long long a, unsigned long long b, unsigned long long c){
    unsigned long long d;
    asm("fma.rn.f32x2 %0, %1, %2, %3;" : "=l"(d) : "l"(a), "l"(b), "l"(c));
    return d;
}

// ================= Kernel 1: A = clip(s_t)@W1a ; Bm = clip(s_t1)@W1b =================
// grid (4, B), 256 threads. Each CTA: 16 rows of both A and Bm.
__global__ void __launch_bounds__(256) precompute_kernel(
    const float* __restrict__ slots_t, const float* __restrict__ slots_t1,
    const float* __restrict__ W1)
{
    __shared__ float s0[16][256];
    __shared__ float s1[16][256];
    const int ig = blockIdx.x, b = blockIdx.y;
    const int tid = threadIdx.x;
    const int rowbase = b*Nn + ig*16;          // first row index
    const int gbase = rowbase * Dd;

    for (int idx = tid; idx < 16*256; idx += 256){
        int r = idx >> 8, k = idx & 255;
        s0[r][k] = clip50(slots_t [gbase + idx]);
        s1[r][k] = clip50(slots_t1[gbase + idx]);
    }
    __syncthreads();

    const int c = tid;                          // output column
    float accA[16], accB[16];
    #pragma unroll
    for (int i=0;i<16;i++){ accA[i]=0.f; accB[i]=0.f; }

    for (int k = 0; k < 256; k += 4){
        float wA[4], wB[4];
        #pragma unroll
        for (int u=0;u<4;u++){
            wA[u] = W1[(k+u)*Dd + c];
            wB[u] = W1[(256+k+u)*Dd + c];
        }
        #pragma unroll
        for (int i=0;i<16;i++){
            float4 a  = *reinterpret_cast<const float4*>(&s0[i][k]);
            float4 bb = *reinterpret_cast<const float4*>(&s1[i][k]);
            accA[i] = fmaf(a.x , wA[0], accA[i]);
            accA[i] = fmaf(a.y , wA[1], accA[i]);
            accA[i] = fmaf(a.z , wA[2], accA[i]);
            accA[i] = fmaf(a.w , wA[3], accA[i]);
            accB[i] = fmaf(bb.x, wB[0], accB[i]);
            accB[i] = fmaf(bb.y, wB[1], accB[i]);
            accB[i] = fmaf(bb.z, wB[2], accB[i]);
            accB[i] = fmaf(bb.w, wB[3], accB[i]);
        }
    }
    #pragma unroll
    for (int i=0;i<16;i++){
        g_A [(rowbase+i)*Dd + c] = accA[i];
        g_Bm[(rowbase+i)*Dd + c] = accB[i];
    }
}

// ================= Kernel 2: per (b,i) compute scores for all j, write log_alpha ===========
// smem float offsets
#define OFF_ST1T 0              // [256][66] transposed clipped s_t1[b]  (16896)
#define OFF_H    16896          // [64][256] layer-1 output              (16384)
#define OFF_SCR  33280          // scratch: W1c tile [32][256] (8192) OR (W2 tile [64][64] + H2 [64][65])
#define OFF_W2T  33280          // [64][64]  (4096)
#define OFF_H2   37376          // [64][65]  (4160)
#define OFF_STI  41728          // [256] clipped s_t[b,i]
#define OFF_AB   41984          // [256] A row + b1
#define OFF_W3   42240          // [64]
#define OFF_B2   42304          // [64]
#define SMEM_FLOATS 42368
#define SMEM_BYTES  (SMEM_FLOATS*4)

__global__ void __launch_bounds__(256, 1) score_kernel(
    const float* __restrict__ slots_t, const float* __restrict__ slots_t1,
    const float* __restrict__ alive_t, const float* __restrict__ alive_t1,
    const float* __restrict__ W1, const float* __restrict__ b1,
    const float* __restrict__ W2, const float* __restrict__ b2,
    const float* __restrict__ W3, const float* __restrict__ b3)
{
    extern __shared__ float sm[];
    float* ST1T = sm + OFF_ST1T;   // stride 66
    float* H    = sm + OFF_H;      // stride 256
    float* SCR  = sm + OFF_SCR;    // W1c tile during GEMM1
    float* W2T  = sm + OFF_W2T;
    float* H2   = sm + OFF_H2;     // stride 65
    float* STI  = sm + OFF_STI;
    float* AB   = sm + OFF_AB;
    float* W3S  = sm + OFF_W3;
    float* B2S  = sm + OFF_B2;

    const int i = blockIdx.x, b = blockIdx.y;
    const int tid = threadIdx.x;
    const int tx = tid & 31, ty = tid >> 5;
    const int jb = ty * 8;                     // 8 rows per warp group

    // ---- fill phase ----
    STI[tid] = clip50(slots_t[(b*Nn + i)*Dd + tid]);
    AB[tid]  = g_A[(b*Nn + i)*Dd + tid] + b1[tid];
    if (tid < 64){ W3S[tid] = W3[tid]; B2S[tid] = b2[tid]; }
    for (int idx = tid; idx < Nn*Dd; idx += 256){
        int j = idx >> 8, k = idx & 255;
        ST1T[k*66 + j] = clip50(slots_t1[b*Nn*Dd + idx]);
    }
    __syncthreads();

    // ---- GEMM1: H[j][c] = relu(A[i]+Bm[j]+b1 + |s_ti - s_t1j| @ W1c) ----
    unsigned long long acc[4][8];
    #pragma unroll
    for (int rp=0;rp<4;rp++)
        #pragma unroll
        for (int cc=0;cc<8;cc++) acc[rp][cc] = 0ULL;

    const unsigned long long NEG1 = 0xBF800000BF800000ULL;  // (-1.f,-1.f)
    const unsigned long long ABSM = 0x7FFFFFFF7FFFFFFFULL;

    for (int kt = 0; kt < 256; kt += 32){
        __syncthreads();
        for (int idx = tid; idx < 32*256; idx += 256)
            SCR[idx] = W1[(512 + kt + (idx >> 8))*Dd + (idx & 255)];
        __syncthreads();

        #pragma unroll 4
        for (int kk = 0; kk < 32; kk++){
            const int k = kt + kk;
            float a = STI[k];
            unsigned long long a2 = pack2(a, a);
            unsigned long long dd[4];
            #pragma unroll
            for (int rp=0;rp<4;rp++){
                unsigned long long s2 = *reinterpret_cast<const unsigned long long*>(&ST1T[k*66 + jb + 2*rp]);
                dd[rp] = fma2r(s2, NEG1, a2) & ABSM;   // |s_ti - s_t1j| as f32x2 pair
            }
            #pragma unroll
            for (int cc=0;cc<8;cc++){
                float wv = SCR[kk*256 + tx + 32*cc];
                unsigned long long w2 = pack2(wv, wv);
                #pragma unroll
                for (int rp=0;rp<4;rp++) fma2(acc[rp][cc], dd[rp], w2);
            }
        }
    }

    // epilogue: add A+b1 and Bm[j], relu, write H
    #pragma unroll
    for (int rp=0;rp<4;rp++){
        const int j0 = jb + 2*rp;
        #pragma unroll
        for (int cc=0;cc<8;cc++){
            const int c = tx + 32*cc;
            float lo, hi; unpack2(acc[rp][cc], lo, hi);
            float base = AB[c];
            float h0 = fmaxf(lo + base + g_Bm[(b*Nn + j0  )*Dd + c], 0.f);
            float h1 = fmaxf(hi + base + g_Bm[(b*Nn + j0+1)*Dd + c], 0.f);
            H[(j0  )*256 + c] = h0;
            H[(j0+1)*256 + c] = h1;
        }
    }
    __syncthreads();

    // ---- GEMM2: H2 = relu(H @ W2 + b2); rows jb..jb+7, col-pair 2*tx ----
    unsigned long long acc2[8];
    #pragma unroll
    for (int rr=0;rr<8;rr++) acc2[rr] = 0ULL;

    for (int kt = 0; kt < 256; kt += 64){
        __syncthreads();
        for (int idx = tid; idx < 64*64; idx += 256)
            W2T[idx] = W2[(kt + (idx >> 6))*64 + (idx & 63)];
        __syncthreads();

        #pragma unroll 4
        for (int kk = 0; kk < 64; kk++){
            const int k = kt + kk;
            unsigned long long wp = *reinterpret_cast<const unsigned long long*>(&W2T[kk*64 + 2*tx]);
            #pragma unroll
            for (int rr=0;rr<8;rr++){
                float hv = H[(jb+rr)*256 + k];
                unsigned long long h2 = pack2(hv, hv);
                fma2(acc2[rr], h2, wp);
            }
        }
    }
    __syncthreads();   // before H2 writes reuse of scratch region boundary

    #pragma unroll
    for (int rr=0;rr<8;rr++){
        float lo, hi; unpack2(acc2[rr], lo, hi);
        float v0 = fmaxf(lo + B2S[2*tx  ], 0.f);
        float v1 = fmaxf(hi + B2S[2*tx+1], 0.f);
        H2[(jb+rr)*65 + 2*tx    ] = v0;
        H2[(jb+rr)*65 + 2*tx + 1] = v1;
    }
    __syncthreads();

    // ---- GEMM3 + penalties + log_alpha write ----
    if (tid < 64){
        const int j = tid;
        float s0=0.f,s1=0.f,s2=0.f,s3=0.f;
        #pragma unroll
        for (int c = 0; c < 64; c += 4){
            s0 = fmaf(H2[j*65 + c  ], W3S[c  ], s0);
            s1 = fmaf(H2[j*65 + c+1], W3S[c+1], s1);
            s2 = fmaf(H2[j*65 + c+2], W3S[c+2], s2);
            s3 = fmaf(H2[j*65 + c+3], W3S[c+3], s3);
        }
        float score = (s0+s1)+(s2+s3) + b3[0];
        if (alive_t [b*Nn + i] < 0.5f) score -= PEN;
        if (alive_t1[b*Nn + j] < 0.5f) score -= PEN;
        // la = -clip(-score,-P,P)/TEMP = clip(score,-P,P)*INV_TEMP
        float la = fminf(fmaxf(score, -PEN), PEN) * INV_TEMP;
        g_la[(b*Nn + i)*Nn + j] = la;
    }
}

// ================= Kernel 3: Sinkhorn (20 iters) + argmax + matched ==============
__global__ void __launch_bounds__(512) sinkhorn_kernel(
    const float* __restrict__ alive_t, const float* __restrict__ alive_t1,
    float* __restrict__ out)
{
    __shared__ float la[64][65];
    const int b = blockIdx.x;
    const int tid = threadIdx.x;
    const int lane = tid & 31, w = tid >> 5;   // 16 warps

    for (int idx = tid; idx < 64*64; idx += 512)
        la[idx >> 6][idx & 63] = g_la[b*4096 + idx];
    __syncthreads();

    for (int it = 0; it < 20; it++){
        // rows (logsumexp over j)
        #pragma unroll
        for (int rr = 0; rr < 4; rr++){
            const int i = w*4 + rr;
            float v0 = la[i][lane], v1 = la[i][lane+32];
            float m = fmaxf(v0, v1);
            #pragma unroll
            for (int off = 16; off > 0; off >>= 1) m = fmaxf(m, __shfl_xor_sync(0xffffffffu, m, off));
            float s = expf(v0 - m) + expf(v1 - m);
            #pragma unroll
            for (int off = 16; off > 0; off >>= 1) s += __shfl_xor_sync(0xffffffffu, s, off);
            float lse = m + logf(s);
            la[i][lane]    = v0 - lse;
            la[i][lane+32] = v1 - lse;
        }
        __syncthreads();
        // cols (logsumexp over i)
        #pragma unroll
        for (int rr = 0; rr < 4; rr++){
            const int j = w*4 + rr;
            float v0 = la[lane][j], v1 = la[lane+32][j];
            float m = fmaxf(v0, v1);
            #pragma unroll
            for (int off = 16; off > 0; off >>= 1) m = fmaxf(m, __shfl_xor_sync(0xffffffffu, m, off));
            float s = expf(v0 - m) + expf(v1 - m);
            #pragma unroll
            for (int off = 16; off > 0; off >>= 1) s += __shfl_xor_sync(0xffffffffu, s, off);
            float lse = m + logf(s);
            la[lane][j]    = v0 - lse;
            la[lane+32][j] = v1 - lse;
        }
        __syncthreads();
    }

    // argmax over j (first-max tie break, matching jnp.argmax), confidence, matched
    #pragma unroll
    for (int rr = 0; rr < 4; rr++){
        const int i = w*4 + rr;
        float v0 = la[i][lane], v1 = la[i][lane+32];
        float bv; int bi;
        if (v1 > v0){ bv = v1; bi = lane + 32; } else { bv = v0; bi = lane; }
        #pragma unroll
        for (int off = 16; off > 0; off >>= 1){
            float ov = __shfl_xor_sync(0xffffffffu, bv, off);
            int   oi = __shfl_xor_sync(0xffffffffu, bi, off);
            if (ov > bv || (ov == bv && oi < bi)){ bv = ov; bi = oi; }
        }
        if (lane == 0){
            float conf = expf(bv);
            float at  = alive_t [b*Nn + i];
            float at1 = alive_t1[b*Nn + bi];
            float matched = (at > 0.5f && at1 > 0.5f && conf > 0.3f) ? 1.f : 0.f;
            out[b*Nn + i]           = (float)bi;   // perm
            out[Bb*Nn + b*Nn + i]   = matched;     // matched
        }
    }
}

// ================= launch =================
extern "C" void kernel_launch(void* const* d_in, const int* in_sizes, int n_in,
                              void* d_out, int out_size)
{
    const float* slots_t  = (const float*)d_in[0];
    const float* slots_t1 = (const float*)d_in[1];
    const float* alive_t  = (const float*)d_in[2];
    const float* alive_t1 = (const float*)d_in[3];
    const float* W1 = (const float*)d_in[4];
    const float* b1 = (const float*)d_in[5];
    const float* W2 = (const float*)d_in[6];
    const float* b2 = (const float*)d_in[7];
    const float* W3 = (const float*)d_in[8];
    const float* b3 = (const float*)d_in[9];
    float* out = (float*)d_out;

    cudaFuncSetAttribute(score_kernel, cudaFuncAttributeMaxDynamicSharedMemorySize, SMEM_BYTES);

    precompute_kernel<<<dim3(4, Bb), 256>>>(slots_t, slots_t1, W1);
    score_kernel<<<dim3(Nn, Bb), 256, SMEM_BYTES>>>(slots_t, slots_t1, alive_t, alive_t1,
                                                    W1, b1, W2, b2, W3, b3);
    sinkhorn_kernel<<<Bb, 512>>>(alive_t, alive_t1, out);
}

// round 2
// speedup vs baseline: 1.2636x; 1.2636x over previous
#include <cuda_runtime.h>
#include <math.h>
#include <stdint.h>

#define Bb 32
#define Nn 64
#define Dd 256
#define PEN 10000.0f
#define INV_TEMP 20.0f   // 1/0.05

// ---------------- device scratch (no allocations allowed) ----------------
__device__ float g_A [Bb*Nn*Dd];   // s_t  @ W1a                 (2 MB)
__device__ float g_Bm[Bb*Nn*Dd];   // s_t1 @ W1b + b1            (2 MB)
__device__ float g_la[Bb*Nn*Nn];   // log_alpha                  (512 KB)

__device__ __forceinline__ float clip50(float x){ return fminf(fmaxf(x, -50.f), 50.f); }

__device__ __forceinline__ unsigned long long pack2(float x, float y){
    unsigned long long r;
    asm("mov.b64 %0, {%1, %2};" : "=l"(r) : "f"(x), "f"(y));
    return r;
}
__device__ __forceinline__ void unpack2(unsigned long long v, float &lo, float &hi){
    asm("mov.b64 {%0, %1}, %2;" : "=f"(lo), "=f"(hi) : "l"(v));
}
__device__ __forceinline__ void fma2(unsigned long long &acc, unsigned long long a, unsigned long long b){
    asm("fma.rn.f32x2 %0, %1, %2, %0;" : "+l"(acc) : "l"(a), "l"(b));
}
__device__ __forceinline__ unsigned long long fma2r(unsigned long long a, unsigned long long b, unsigned long long c){
    unsigned long long d;
    asm("fma.rn.f32x2 %0, %1, %2, %3;" : "=l"(d) : "l"(a), "l"(b), "l"(c));
    return d;
}
__device__ __forceinline__ unsigned long long lds64(const float* p){
    return *reinterpret_cast<const unsigned long long*>(p);
}
__device__ __forceinline__ void cp_async16(uint32_t dst, const void* src){
    asm volatile("cp.async.ca.shared.global [%0], [%1], 16;" :: "r"(dst), "l"(src));
}
#define CP_COMMIT() asm volatile("cp.async.commit_group;")
#define CP_WAIT1()  asm volatile("cp.async.wait_group 1;")
#define CP_WAIT0()  asm volatile("cp.async.wait_group 0;")

// ================= Kernel 1: A = clip(s_t)@W1a ; Bm = clip(s_t1)@W1b + b1 =============
// grid (4, B), 256 threads. CTA handles 16 rows (8 row-pairs) of both outputs, fma2.
__global__ void __launch_bounds__(256) precompute_kernel(
    const float* __restrict__ slots_t, const float* __restrict__ slots_t1,
    const float* __restrict__ W1, const float* __restrict__ b1)
{
    __shared__ float s0T[256][18];   // [k][row], pad 18: 2-way write conflict max
    __shared__ float s1T[256][18];
    const int ig = blockIdx.x, b = blockIdx.y;
    const int tid = threadIdx.x;
    const int rowbase = b*Nn + ig*16;
    const int gbase = rowbase * Dd;

    for (int idx = tid; idx < 16*256; idx += 256){
        int r = idx >> 8, k = idx & 255;
        s0T[k][r] = clip50(slots_t [gbase + idx]);
        s1T[k][r] = clip50(slots_t1[gbase + idx]);
    }
    __syncthreads();

    const int c = tid;
    const float b1v = b1[c];
    unsigned long long accA[8], accB[8];
    #pragma unroll
    for (int i=0;i<8;i++){ accA[i]=0ULL; accB[i]=0ULL; }

    #pragma unroll 4
    for (int k = 0; k < 256; k++){
        float wA = __ldg(&W1[k*Dd + c]);
        float wB = __ldg(&W1[(256+k)*Dd + c]);
        unsigned long long wA2 = pack2(wA, wA);
        unsigned long long wB2 = pack2(wB, wB);
        #pragma unroll
        for (int rp=0; rp<8; rp++){
            fma2(accA[rp], lds64(&s0T[k][2*rp]), wA2);
            fma2(accB[rp], lds64(&s1T[k][2*rp]), wB2);
        }
    }
    #pragma unroll
    for (int rp=0; rp<8; rp++){
        float lo, hi;
        unpack2(accA[rp], lo, hi);
        g_A [(rowbase+2*rp  )*Dd + c] = lo;
        g_A [(rowbase+2*rp+1)*Dd + c] = hi;
        unpack2(accB[rp], lo, hi);
        g_Bm[(rowbase+2*rp  )*Dd + c] = lo + b1v;
        g_Bm[(rowbase+2*rp+1)*Dd + c] = hi + b1v;
    }
}

// ================= Kernel 2: per (b,i) scores for all j -> log_alpha ===============
// smem float offsets
#define OFF_ST1T 0              // [256][66] transposed clipped s_t1[b]      (16896)
#define OFF_H    16896          // [64][256] layer-1 output                  (16384)
#define OFF_SCR  33280          // 2x [32][256] W1c tile ping-pong  OR  W2 pair layout (16384)
#define OFF_H2   49664          // [64][65]                                  (4160)
#define OFF_STI  53824          // [256]
#define OFF_AB   54080          // [256]  g_A row (b1 folded into g_Bm)
#define OFF_W3   54336          // [64]
#define OFF_B2   54400          // [64]
#define SMEM_FLOATS 54464
#define SMEM_BYTES  (SMEM_FLOATS*4)

__global__ void __launch_bounds__(256, 1) score_kernel(
    const float* __restrict__ slots_t, const float* __restrict__ slots_t1,
    const float* __restrict__ alive_t, const float* __restrict__ alive_t1,
    const float* __restrict__ W1, const float* __restrict__ b1,
    const float* __restrict__ W2, const float* __restrict__ b2,
    const float* __restrict__ W3, const float* __restrict__ b3)
{
    extern __shared__ float sm[];
    float* ST1T = sm + OFF_ST1T;   // stride 66
    float* H    = sm + OFF_H;      // stride 256
    float* SCR  = sm + OFF_SCR;
    float* H2   = sm + OFF_H2;     // stride 65
    float* STI  = sm + OFF_STI;
    float* AB   = sm + OFF_AB;
    float* W3S  = sm + OFF_W3;
    float* B2S  = sm + OFF_B2;
    unsigned long long* W2P = reinterpret_cast<unsigned long long*>(sm + OFF_SCR); // [128][64]

    const int i = blockIdx.x, b = blockIdx.y;
    const int tid = threadIdx.x;
    const int tx = tid & 31, ty = tid >> 5;
    const int jb = ty * 8;                     // 8 j rows per warp

    const uint32_t scr_smem = (uint32_t)__cvta_generic_to_shared(SCR);
    const float* W1c = W1 + 512*Dd;

    // ---- prologue: prefetch W1c tiles 0 and 1 via cp.async ----
    {
        #pragma unroll
        for (int ch = 0; ch < 8; ch++){
            int off = ch*4096 + tid*16;        // byte offset within 32KB tile
            cp_async16(scr_smem + off,          (const char*)W1c + off);
        }
        CP_COMMIT();
        #pragma unroll
        for (int ch = 0; ch < 8; ch++){
            int off = ch*4096 + tid*16;
            cp_async16(scr_smem + 32768 + off,  (const char*)W1c + 32768 + off);
        }
        CP_COMMIT();
    }

    // ---- fill phase ----
    STI[tid] = clip50(slots_t[(b*Nn + i)*Dd + tid]);
    AB[tid]  = g_A[(b*Nn + i)*Dd + tid];
    if (tid < 64){ W3S[tid] = W3[tid]; B2S[tid] = b2[tid]; }
    for (int idx = tid; idx < Nn*Dd; idx += 256){
        int j = idx >> 8, k = idx & 255;
        ST1T[k*66 + j] = clip50(slots_t1[b*Nn*Dd + idx]);
    }

    // ---- GEMM1: H[j][c] = relu(A[i]+Bm[j]+b1 + |s_ti - s_t1j| @ W1c) ----
    unsigned long long acc[4][8];
    #pragma unroll
    for (int rp=0;rp<4;rp++)
        #pragma unroll
        for (int cc=0;cc<8;cc++) acc[rp][cc] = 0ULL;

    const unsigned long long NEG1 = 0xBF800000BF800000ULL;  // (-1.f,-1.f)
    const unsigned long long ABSM = 0x7FFFFFFF7FFFFFFFULL;

    for (int t = 0; t < 8; t++){
        if (t < 6) { CP_WAIT1(); } else { CP_WAIT0(); }
        __syncthreads();
        const float* SCRb = SCR + (t & 1) * 8192;
        const int kt = t * 32;

        #pragma unroll 8
        for (int kk = 0; kk < 32; kk++){
            const int k = kt + kk;
            float a = STI[k];
            unsigned long long a2 = pack2(a, a);
            unsigned long long dd[4];
            #pragma unroll
            for (int rp=0;rp<4;rp++){
                unsigned long long s2 = lds64(&ST1T[k*66 + jb + 2*rp]);
                dd[rp] = fma2r(s2, NEG1, a2) & ABSM;   // |s_ti - s_t1j| pair
            }
            #pragma unroll
            for (int cc=0;cc<8;cc++){
                float wv = SCRb[kk*256 + tx + 32*cc];
                unsigned long long w2 = pack2(wv, wv);
                #pragma unroll
                for (int rp=0;rp<4;rp++) fma2(acc[rp][cc], dd[rp], w2);
            }
        }
        __syncthreads();
        if (t + 2 < 8){
            const int tn = t + 2;
            #pragma unroll
            for (int ch = 0; ch < 8; ch++){
                int off = ch*4096 + tid*16;
                cp_async16(scr_smem + (tn & 1)*32768 + off,
                           (const char*)W1c + tn*32768 + off);
            }
            CP_COMMIT();
        }
    }

    // epilogue: add A row and (Bm[j]+b1), relu, write H
    #pragma unroll
    for (int rp=0;rp<4;rp++){
        const int j0 = jb + 2*rp;
        #pragma unroll
        for (int cc=0;cc<8;cc++){
            const int c = tx + 32*cc;
            float lo, hi; unpack2(acc[rp][cc], lo, hi);
            float base = AB[c];
            float h0 = fmaxf(lo + base + g_Bm[(b*Nn + j0  )*Dd + c], 0.f);
            float h1 = fmaxf(hi + base + g_Bm[(b*Nn + j0+1)*Dd + c], 0.f);
            H[(j0  )*256 + c] = h0;
            H[(j0+1)*256 + c] = h1;
        }
    }
    __syncthreads();   // H ready; SCR free (all tile reads done)

    // ---- build W2 pair layout in SCR: W2P[kp][m] = (W2[2kp][m], W2[2kp+1][m]) ----
    for (int idx = tid; idx < 128*64; idx += 256){
        int kp = idx >> 6, m = idx & 63;
        W2P[idx] = pack2(W2[(2*kp)*64 + m], W2[(2*kp+1)*64 + m]);
    }
    __syncthreads();

    // ---- GEMM2: H2 = relu(H @ W2 + b2), k-paired fma2 ----
    // thread: rows jb..jb+7, cols m0=tx, m1=tx+32
    unsigned long long acc2[8][2];
    #pragma unroll
    for (int rr=0;rr<8;rr++){ acc2[rr][0]=0ULL; acc2[rr][1]=0ULL; }

    #pragma unroll 8
    for (int kp = 0; kp < 128; kp++){
        unsigned long long wp0 = W2P[kp*64 + tx];
        unsigned long long wp1 = W2P[kp*64 + 32 + tx];
        #pragma unroll
        for (int rr=0;rr<8;rr++){
            unsigned long long hp = lds64(&H[(jb+rr)*256 + 2*kp]);  // (H[j][2kp],H[j][2kp+1])
            fma2(acc2[rr][0], hp, wp0);
            fma2(acc2[rr][1], hp, wp1);
        }
    }

    #pragma unroll
    for (int rr=0;rr<8;rr++){
        float lo, hi;
        unpack2(acc2[rr][0], lo, hi);
        H2[(jb+rr)*65 + tx     ] = fmaxf(lo + hi + B2S[tx     ], 0.f);
        unpack2(acc2[rr][1], lo, hi);
        H2[(jb+rr)*65 + tx + 32] = fmaxf(lo + hi + B2S[tx + 32], 0.f);
    }
    __syncthreads();

    // ---- GEMM3 + penalties + log_alpha write ----
    if (tid < 64){
        const int j = tid;
        float s0=0.f,s1=0.f,s2=0.f,s3=0.f;
        #pragma unroll
        for (int c = 0; c < 64; c += 4){
            s0 = fmaf(H2[j*65 + c  ], W3S[c  ], s0);
            s1 = fmaf(H2[j*65 + c+1], W3S[c+1], s1);
            s2 = fmaf(H2[j*65 + c+2], W3S[c+2], s2);
            s3 = fmaf(H2[j*65 + c+3], W3S[c+3], s3);
        }
        float score = (s0+s1)+(s2+s3) + b3[0];
        if (alive_t [b*Nn + i] < 0.5f) score -= PEN;
        if (alive_t1[b*Nn + j] < 0.5f) score -= PEN;
        float la = fminf(fmaxf(score, -PEN), PEN) * INV_TEMP;
        g_la[(b*Nn + i)*Nn + j] = la;
    }
}

// ================= Kernel 3: Sinkhorn (20 iters) + argmax + matched ==============
__global__ void __launch_bounds__(512) sinkhorn_kernel(
    const float* __restrict__ alive_t, const float* __restrict__ alive_t1,
    float* __restrict__ out)
{
    __shared__ float la[64][65];
    const int b = blockIdx.x;
    const int tid = threadIdx.x;
    const int lane = tid & 31, w = tid >> 5;   // 16 warps

    for (int idx = tid; idx < 64*64; idx += 512)
        la[idx >> 6][idx & 63] = g_la[b*4096 + idx];
    __syncthreads();

    for (int it = 0; it < 20; it++){
        #pragma unroll
        for (int rr = 0; rr < 4; rr++){
            const int i = w*4 + rr;
            float v0 = la[i][lane], v1 = la[i][lane+32];
            float m = fmaxf(v0, v1);
            #pragma unroll
            for (int off = 16; off > 0; off >>= 1) m = fmaxf(m, __shfl_xor_sync(0xffffffffu, m, off));
            float s = expf(v0 - m) + expf(v1 - m);
            #pragma unroll
            for (int off = 16; off > 0; off >>= 1) s += __shfl_xor_sync(0xffffffffu, s, off);
            float lse = m + logf(s);
            la[i][lane]    = v0 - lse;
            la[i][lane+32] = v1 - lse;
        }
        __syncthreads();
        #pragma unroll
        for (int rr = 0; rr < 4; rr++){
            const int j = w*4 + rr;
            float v0 = la[lane][j], v1 = la[lane+32][j];
            float m = fmaxf(v0, v1);
            #pragma unroll
            for (int off = 16; off > 0; off >>= 1) m = fmaxf(m, __shfl_xor_sync(0xffffffffu, m, off));
            float s = expf(v0 - m) + expf(v1 - m);
            #pragma unroll
            for (int off = 16; off > 0; off >>= 1) s += __shfl_xor_sync(0xffffffffu, s, off);
            float lse = m + logf(s);
            la[lane][j]    = v0 - lse;
            la[lane+32][j] = v1 - lse;
        }
        __syncthreads();
    }

    #pragma unroll
    for (int rr = 0; rr < 4; rr++){
        const int i = w*4 + rr;
        float v0 = la[i][lane], v1 = la[i][lane+32];
        float bv; int bi;
        if (v1 > v0){ bv = v1; bi = lane + 32; } else { bv = v0; bi = lane; }
        #pragma unroll
        for (int off = 16; off > 0; off >>= 1){
            float ov = __shfl_xor_sync(0xffffffffu, bv, off);
            int   oi = __shfl_xor_sync(0xffffffffu, bi, off);
            if (ov > bv || (ov == bv && oi < bi)){ bv = ov; bi = oi; }
        }
        if (lane == 0){
            float conf = expf(bv);
            float at  = alive_t [b*Nn + i];
            float at1 = alive_t1[b*Nn + bi];
            float matched = (at > 0.5f && at1 > 0.5f && conf > 0.3f) ? 1.f : 0.f;
            out[b*Nn + i]           = (float)bi;   // perm
            out[Bb*Nn + b*Nn + i]   = matched;     // matched
        }
    }
}

// ================= launch =================
extern "C" void kernel_launch(void* const* d_in, const int* in_sizes, int n_in,
                              void* d_out, int out_size)
{
    const float* slots_t  = (const float*)d_in[0];
    const float* slots_t1 = (const float*)d_in[1];
    const float* alive_t  = (const float*)d_in[2];
    const float* alive_t1 = (const float*)d_in[3];
    const float* W1 = (const float*)d_in[4];
    const float* b1 = (const float*)d_in[5];
    const float* W2 = (const float*)d_in[6];
    const float* b2 = (const float*)d_in[7];
    const float* W3 = (const float*)d_in[8];
    const float* b3 = (const float*)d_in[9];
    float* out = (float*)d_out;

    cudaFuncSetAttribute(score_kernel, cudaFuncAttributeMaxDynamicSharedMemorySize, SMEM_BYTES);

    precompute_kernel<<<dim3(4, Bb), 256>>>(slots_t, slots_t1, W1, b1);
    score_kernel<<<dim3(Nn, Bb), 256, SMEM_BYTES>>>(slots_t, slots_t1, alive_t, alive_t1,
                                                    W1, b1, W2, b2, W3, b3);
    sinkhorn_kernel<<<Bb, 512>>>(alive_t, alive_t1, out);
}

// round 4
// speedup vs baseline: 1.4535x; 1.1503x over previous
#include <cuda_runtime.h>
#include <math.h>
#include <stdint.h>

#define Bb 32
#define Nn 64
#define Dd 256
#define PEN 10000.0f
#define INV_TEMP 20.0f   // 1/0.05

typedef unsigned long long u64;

// ---------------- device scratch (no allocations allowed) ----------------
__device__ float g_A  [Bb*Nn*Dd];   // s_t  @ W1a                   (2 MB)
__device__ float g_Bm [Bb*Nn*Dd];   // s_t1 @ W1b + b1              (2 MB)
__device__ float g_s1T[Bb*Dd*Nn];   // clipped s_t1 transposed [b][k][j] (2 MB)
__device__ float g_la [Bb*Nn*Nn];   // log_alpha                    (512 KB)

__device__ __forceinline__ float clip50(float x){ return fminf(fmaxf(x, -50.f), 50.f); }

__device__ __forceinline__ u64 pack2(float x, float y){
    u64 r; asm("mov.b64 %0, {%1, %2};" : "=l"(r) : "f"(x), "f"(y)); return r;
}
__device__ __forceinline__ void unpack2(u64 v, float &lo, float &hi){
    asm("mov.b64 {%0, %1}, %2;" : "=f"(lo), "=f"(hi) : "l"(v));
}
__device__ __forceinline__ void fma2(u64 &acc, u64 a, u64 b){
    asm("fma.rn.f32x2 %0, %1, %2, %0;" : "+l"(acc) : "l"(a), "l"(b));
}
__device__ __forceinline__ u64 fma2r(u64 a, u64 b, u64 c){
    u64 d; asm("fma.rn.f32x2 %0, %1, %2, %3;" : "=l"(d) : "l"(a), "l"(b), "l"(c)); return d;
}
__device__ __forceinline__ u64 lds64(const float* p){
    return *reinterpret_cast<const u64*>(p);
}
__device__ __forceinline__ void cp_async16(uint32_t dst, const void* src){
    asm volatile("cp.async.ca.shared.global [%0], [%1], 16;" :: "r"(dst), "l"(src));
}
#define CP_COMMIT() asm volatile("cp.async.commit_group;")
#define CP_WAIT2()  asm volatile("cp.async.wait_group 2;")
#define CP_WAIT1()  asm volatile("cp.async.wait_group 1;")
#define CP_WAIT0()  asm volatile("cp.async.wait_group 0;")

// ================= Kernel 1: A = clip(s_t)@W1a ; Bm = clip(s_t1)@W1b + b1 ============
// Also emits g_s1T (clipped transposed s_t1). grid (4,B), 512 threads.
// WT stage = 32 k-rows of W1a (32KB) + 32 k-rows of W1b (32KB) = 65536 B = 16384 floats.
#define P_S0T 0                 // [256][18]
#define P_S1T 4608              // [256][18]
#define P_WT  9216              // [2 buf][16384 floats]
#define P_SMEM_FLOATS (9216 + 32768)
#define P_SMEM_BYTES  (P_SMEM_FLOATS*4)

__global__ void __launch_bounds__(512, 1) precompute_kernel(
    const float* __restrict__ slots_t, const float* __restrict__ slots_t1,
    const float* __restrict__ W1, const float* __restrict__ b1)
{
    extern __shared__ float psm[];
    float* s0T = psm + P_S0T;
    float* s1T = psm + P_S1T;
    float* WT  = psm + P_WT;
    const int ig = blockIdx.x, b = blockIdx.y;
    const int tid = threadIdx.x;
    const int rowbase = b*Nn + ig*16;
    const int gbase = rowbase * Dd;
    const uint32_t wt_smem = (uint32_t)__cvta_generic_to_shared(WT);

    // prefetch W tiles 0 and 1 (each stage: 32 k-rows of W1a and W1b)
    #pragma unroll
    for (int t = 0; t < 2; t++){
        #pragma unroll
        for (int u = 0; u < 4; u++){
            int off = u*8192 + tid*16;
            cp_async16(wt_smem + t*65536 + off,         (const char*)(W1 + t*32*Dd) + off);
            cp_async16(wt_smem + t*65536 + 32768 + off, (const char*)(W1 + (256 + t*32)*Dd) + off);
        }
        CP_COMMIT();
    }

    // fill transposed clipped s-tiles (16 rows each)
    #pragma unroll
    for (int n = 0; n < 8; n++){
        int idx = tid + n*512;
        int r = idx >> 8, k = idx & 255;
        s0T[k*18 + r] = clip50(slots_t [gbase + idx]);
        s1T[k*18 + r] = clip50(slots_t1[gbase + idx]);
    }
    __syncthreads();

    // write g_s1T [b][k][j]  (j = ig*16 + r)
    #pragma unroll
    for (int n = 0; n < 8; n++){
        int idx = tid + n*512;
        int r = idx & 15, k = idx >> 4;
        g_s1T[(b*256 + k)*64 + ig*16 + r] = s1T[k*18 + r];
    }

    const int c = tid & 255;
    const int rb = (tid >> 8) * 8;      // local rows rb..rb+7 (4 pairs)
    u64 accA[4], accB[4];
    #pragma unroll
    for (int p=0;p<4;p++){ accA[p]=0ULL; accB[p]=0ULL; }

    for (int t = 0; t < 8; t++){
        if (t < 7) { CP_WAIT1(); } else { CP_WAIT0(); }
        __syncthreads();
        const float* WA = WT + (t&1)*16384;
        const float* WB = WA + 8192;
        #pragma unroll 8
        for (int kk = 0; kk < 32; kk++){
            const int k = t*32 + kk;
            float wA = WA[kk*256 + c];
            float wB = WB[kk*256 + c];
            u64 wA2 = pack2(wA, wA);
            u64 wB2 = pack2(wB, wB);
            #pragma unroll
            for (int p=0;p<4;p++){
                fma2(accA[p], lds64(&s0T[k*18 + rb + 2*p]), wA2);
                fma2(accB[p], lds64(&s1T[k*18 + rb + 2*p]), wB2);
            }
        }
        __syncthreads();
        if (t + 2 < 8){
            const int tn = t + 2;
            #pragma unroll
            for (int u = 0; u < 4; u++){
                int off = u*8192 + tid*16;
                cp_async16(wt_smem + (tn&1)*65536 + off,         (const char*)(W1 + tn*32*Dd) + off);
                cp_async16(wt_smem + (tn&1)*65536 + 32768 + off, (const char*)(W1 + (256 + tn*32)*Dd) + off);
            }
            CP_COMMIT();
        }
    }

    const float b1v = b1[c];
    #pragma unroll
    for (int p=0;p<4;p++){
        float lo, hi;
        unpack2(accA[p], lo, hi);
        g_A [(rowbase + rb + 2*p    )*Dd + c] = lo;
        g_A [(rowbase + rb + 2*p + 1)*Dd + c] = hi;
        unpack2(accB[p], lo, hi);
        g_Bm[(rowbase + rb + 2*p    )*Dd + c] = lo + b1v;
        g_Bm[(rowbase + rb + 2*p + 1)*Dd + c] = hi + b1v;
    }
}

// ================= Kernel 2: per (b,i) scores for all j -> log_alpha ===============
#define SOFF_ST1T 0        // u64 view [256][32]  (16384 floats)
#define SOFF_H    16384    // [64][256]
#define SOFF_SCR  32768    // 2 x [32][256] W1c ping-pong; later W2P u64[128][64]
#define SOFF_DD   49152    // u64 [2][32][32] DD buffers; later H2 [64][64]
#define SOFF_STIP 53248    // u64 [256] (a,a) pairs
#define SOFF_AB   53760    // [256]
#define SOFF_W3   54016    // [64]
#define SOFF_B2   54080    // [64]
#define S_SMEM_FLOATS 54144
#define S_SMEM_BYTES  (S_SMEM_FLOATS*4)   // 216576

__global__ void __launch_bounds__(512, 1) score_kernel(
    const float* __restrict__ slots_t,
    const float* __restrict__ alive_t, const float* __restrict__ alive_t1,
    const float* __restrict__ W1,
    const float* __restrict__ W2, const float* __restrict__ b2,
    const float* __restrict__ W3, const float* __restrict__ b3)
{
    extern __shared__ float sm[];
    float* H    = sm + SOFF_H;
    float* SCR  = sm + SOFF_SCR;
    float* AB   = sm + SOFF_AB;
    float* W3S  = sm + SOFF_W3;
    float* B2S  = sm + SOFF_B2;
    u64* ST1Tu = reinterpret_cast<u64*>(sm + SOFF_ST1T);
    u64* DDu   = reinterpret_cast<u64*>(sm + SOFF_DD);
    u64* STIPu = reinterpret_cast<u64*>(sm + SOFF_STIP);

    const int i = blockIdx.x, b = blockIdx.y;
    const int tid = threadIdx.x;
    const int tx = tid & 31, w = tid >> 5;
    const int jg = w & 7;        // j group: rows jg*8..jg*8+7 (jp = jg*4..jg*4+3)
    const int cg = w >> 3;       // c group: cols cg*128..cg*128+127

    const uint32_t st1t_smem = (uint32_t)__cvta_generic_to_shared(sm + SOFF_ST1T);
    const uint32_t scr_smem  = (uint32_t)__cvta_generic_to_shared(SCR);
    const float* W1c = W1 + 512*Dd;
    const float* s1Tsrc = g_s1T + b*16384;

    // ---- prologue cp.async: ST1T (group 0), W1c tile0 (group 1), tile1 (group 2) ----
    #pragma unroll
    for (int u = 0; u < 8; u++){
        int off = u*8192 + tid*16;
        cp_async16(st1t_smem + off, (const char*)s1Tsrc + off);
    }
    CP_COMMIT();
    #pragma unroll
    for (int u = 0; u < 4; u++){
        int off = u*8192 + tid*16;
        cp_async16(scr_smem + off, (const char*)W1c + off);
    }
    CP_COMMIT();
    #pragma unroll
    for (int u = 0; u < 4; u++){
        int off = u*8192 + tid*16;
        cp_async16(scr_smem + 32768 + off, (const char*)W1c + 32768 + off);
    }
    CP_COMMIT();

    // ---- small fills ----
    if (tid < 256){
        float a = clip50(slots_t[(b*Nn + i)*Dd + tid]);
        STIPu[tid] = pack2(a, a);
        AB[tid] = g_A[(b*Nn + i)*Dd + tid];
    } else if (tid < 320){
        W3S[tid - 256] = W3[tid - 256];
    } else if (tid < 384){
        B2S[tid - 320] = b2[tid - 320];
    }

    const u64 NEG1 = 0xBF800000BF800000ULL;
    const u64 ABSM = 0x7FFFFFFF7FFFFFFFULL;

    CP_WAIT2();          // ST1T resident
    __syncthreads();     // STIP/AB visible

    // ---- DD[0] production (kt = 0): DD[kk][jp] = |a_k - s1T[k][2jp..2jp+1]| ----
    {
        u64* DDb = DDu;  // buffer 0
        #pragma unroll
        for (int e = 0; e < 2; e++){
            int idx = tid + e*512;
            int kk = idx >> 5, jp = idx & 31;
            u64 s2 = ST1Tu[kk*32 + jp];
            u64 a2 = STIPu[kk];
            DDb[idx] = fma2r(s2, NEG1, a2) & ABSM;
        }
    }

    // ---- GEMM1 mainloop: H = relu(A_i + Bm_j + |diff| @ W1c) ----
    u64 acc[4][4];
    #pragma unroll
    for (int p=0;p<4;p++)
        #pragma unroll
        for (int q=0;q<4;q++) acc[p][q] = 0ULL;

    for (int t = 0; t < 8; t++){
        if (t < 7) { CP_WAIT1(); } else { CP_WAIT0(); }
        __syncthreads();

        // produce DD for next tile (buffer (t+1)&1)
        if (t < 7){
            const int ktn = (t+1)*32;
            u64* DDb = DDu + ((t+1)&1)*1024;
            #pragma unroll
            for (int e = 0; e < 2; e++){
                int idx = tid + e*512;
                int kk = idx >> 5, jp = idx & 31;
                u64 s2 = ST1Tu[(ktn + kk)*32 + jp];
                u64 a2 = STIPu[ktn + kk];
                DDb[idx] = fma2r(s2, NEG1, a2) & ABSM;
            }
        }

        const float* SCRb = SCR + (t&1)*8192;
        const u64* DDb = DDu + (t&1)*1024;

        #pragma unroll 8
        for (int kk = 0; kk < 32; kk++){
            u64 dd0 = DDb[kk*32 + jg*4 + 0];
            u64 dd1 = DDb[kk*32 + jg*4 + 1];
            u64 dd2 = DDb[kk*32 + jg*4 + 2];
            u64 dd3 = DDb[kk*32 + jg*4 + 3];
            float4 w4 = *reinterpret_cast<const float4*>(&SCRb[kk*256 + cg*128 + 4*tx]);
            u64 w0 = pack2(w4.x, w4.x);
            u64 w1 = pack2(w4.y, w4.y);
            u64 w2p = pack2(w4.z, w4.z);
            u64 w3p = pack2(w4.w, w4.w);
            fma2(acc[0][0], dd0, w0); fma2(acc[0][1], dd0, w1);
            fma2(acc[0][2], dd0, w2p); fma2(acc[0][3], dd0, w3p);
            fma2(acc[1][0], dd1, w0); fma2(acc[1][1], dd1, w1);
            fma2(acc[1][2], dd1, w2p); fma2(acc[1][3], dd1, w3p);
            fma2(acc[2][0], dd2, w0); fma2(acc[2][1], dd2, w1);
            fma2(acc[2][2], dd2, w2p); fma2(acc[2][3], dd2, w3p);
            fma2(acc[3][0], dd3, w0); fma2(acc[3][1], dd3, w1);
            fma2(acc[3][2], dd3, w2p); fma2(acc[3][3], dd3, w3p);
        }
        __syncthreads();
        if (t + 2 < 8){
            const int tn = t + 2;
            #pragma unroll
            for (int u = 0; u < 4; u++){
                int off = u*8192 + tid*16;
                cp_async16(scr_smem + (tn&1)*32768 + off, (const char*)W1c + tn*32768 + off);
            }
            CP_COMMIT();
        }
    }

    // ---- GEMM1 epilogue: add A_i + (Bm_j + b1), relu, write H ----
    const int cbase = cg*128 + 4*tx;
    float4 ab4 = *reinterpret_cast<const float4*>(&AB[cbase]);
    #pragma unroll
    for (int p=0;p<4;p++){
        const int j0 = jg*8 + 2*p;
        float4 bm0 = *reinterpret_cast<const float4*>(&g_Bm[(b*Nn + j0    )*Dd + cbase]);
        float4 bm1 = *reinterpret_cast<const float4*>(&g_Bm[(b*Nn + j0 + 1)*Dd + cbase]);
        float lo, hi;
        float4 h0, h1;
        unpack2(acc[p][0], lo, hi); h0.x = fmaxf(lo + ab4.x + bm0.x, 0.f); h1.x = fmaxf(hi + ab4.x + bm1.x, 0.f);
        unpack2(acc[p][1], lo, hi); h0.y = fmaxf(lo + ab4.y + bm0.y, 0.f); h1.y = fmaxf(hi + ab4.y + bm1.y, 0.f);
        unpack2(acc[p][2], lo, hi); h0.z = fmaxf(lo + ab4.z + bm0.z, 0.f); h1.z = fmaxf(hi + ab4.z + bm1.z, 0.f);
        unpack2(acc[p][3], lo, hi); h0.w = fmaxf(lo + ab4.w + bm0.w, 0.f); h1.w = fmaxf(hi + ab4.w + bm1.w, 0.f);
        *reinterpret_cast<float4*>(&H[(j0    )*256 + cbase]) = h0;
        *reinterpret_cast<float4*>(&H[(j0 + 1)*256 + cbase]) = h1;
    }
    __syncthreads();

    // ---- build W2 pair layout (overlay SCR): W2P[kp][m] = (W2[2kp][m], W2[2kp+1][m]) ----
    u64* W2P = reinterpret_cast<u64*>(sm + SOFF_SCR);
    #pragma unroll
    for (int n = 0; n < 16; n++){
        int idx = tid + n*512;
        int kp = idx >> 6, m = idx & 63;
        W2P[idx] = pack2(W2[(2*kp)*64 + m], W2[(2*kp + 1)*64 + m]);
    }
    __syncthreads();

    // ---- GEMM2: H2 = relu(H @ W2 + b2); warp w owns rows w*4..w*4+3 ----
    const int jb2 = w * 4;
    u64 acc2[4][2];
    #pragma unroll
    for (int rr=0;rr<4;rr++){ acc2[rr][0]=0ULL; acc2[rr][1]=0ULL; }

    #pragma unroll 4
    for (int kp = 0; kp < 128; kp++){
        u64 wp0 = W2P[kp*64 + tx];
        u64 wp1 = W2P[kp*64 + 32 + tx];
        #pragma unroll
        for (int rr=0;rr<4;rr++){
            u64 hp = lds64(&H[(jb2+rr)*256 + 2*kp]);
            fma2(acc2[rr][0], hp, wp0);
            fma2(acc2[rr][1], hp, wp1);
        }
    }
    __syncthreads();   // DD region fully dead; reuse as H2

    float* H2 = sm + SOFF_DD;   // [64][64]
    #pragma unroll
    for (int rr=0;rr<4;rr++){
        float lo, hi;
        unpack2(acc2[rr][0], lo, hi);
        H2[(jb2+rr)*64 + tx     ] = fmaxf(lo + hi + B2S[tx     ], 0.f);
        unpack2(acc2[rr][1], lo, hi);
        H2[(jb2+rr)*64 + tx + 32] = fmaxf(lo + hi + B2S[tx + 32], 0.f);
    }
    __syncthreads();

    // ---- GEMM3 + penalties + log_alpha ----
    {
        const int g = tx >> 3, l = tx & 7;
        const int j = w*4 + g;
        float4 hA = *reinterpret_cast<const float4*>(&H2[j*64 + l*8]);
        float4 hB = *reinterpret_cast<const float4*>(&H2[j*64 + l*8 + 4]);
        float4 wA = *reinterpret_cast<const float4*>(&W3S[l*8]);
        float4 wB = *reinterpret_cast<const float4*>(&W3S[l*8 + 4]);
        float s = hA.x*wA.x + hA.y*wA.y + hA.z*wA.z + hA.w*wA.w
                + hB.x*wB.x + hB.y*wB.y + hB.z*wB.z + hB.w*wB.w;
        s += __shfl_xor_sync(0xffffffffu, s, 4);
        s += __shfl_xor_sync(0xffffffffu, s, 2);
        s += __shfl_xor_sync(0xffffffffu, s, 1);
        if (l == 0){
            float score = s + b3[0];
            if (alive_t [b*Nn + i] < 0.5f) score -= PEN;
            if (alive_t1[b*Nn + j] < 0.5f) score -= PEN;
            float la = fminf(fmaxf(score, -PEN), PEN) * INV_TEMP;
            g_la[(b*Nn + i)*Nn + j] = la;
        }
    }
}

// ================= Kernel 3: Sinkhorn (20 iters) + argmax + matched ==============
__global__ void __launch_bounds__(512) sinkhorn_kernel(
    const float* __restrict__ alive_t, const float* __restrict__ alive_t1,
    float* __restrict__ out)
{
    __shared__ float la[64][65];
    const int b = blockIdx.x;
    const int tid = threadIdx.x;
    const int lane = tid & 31, w = tid >> 5;   // 16 warps

    for (int idx = tid; idx < 64*64; idx += 512)
        la[idx >> 6][idx & 63] = g_la[b*4096 + idx];
    __syncthreads();

    for (int it = 0; it < 20; it++){
        #pragma unroll
        for (int rr = 0; rr < 4; rr++){
            const int i = w*4 + rr;
            float v0 = la[i][lane], v1 = la[i][lane+32];
            float m = fmaxf(v0, v1);
            #pragma unroll
            for (int off = 16; off > 0; off >>= 1) m = fmaxf(m, __shfl_xor_sync(0xffffffffu, m, off));
            float s = expf(v0 - m) + expf(v1 - m);
            #pragma unroll
            for (int off = 16; off > 0; off >>= 1) s += __shfl_xor_sync(0xffffffffu, s, off);
            float lse = m + logf(s);
            la[i][lane]    = v0 - lse;
            la[i][lane+32] = v1 - lse;
        }
        __syncthreads();
        #pragma unroll
        for (int rr = 0; rr < 4; rr++){
            const int j = w*4 + rr;
            float v0 = la[lane][j], v1 = la[lane+32][j];
            float m = fmaxf(v0, v1);
            #pragma unroll
            for (int off = 16; off > 0; off >>= 1) m = fmaxf(m, __shfl_xor_sync(0xffffffffu, m, off));
            float s = expf(v0 - m) + expf(v1 - m);
            #pragma unroll
            for (int off = 16; off > 0; off >>= 1) s += __shfl_xor_sync(0xffffffffu, s, off);
            float lse = m + logf(s);
            la[lane][j]    = v0 - lse;
            la[lane+32][j] = v1 - lse;
        }
        __syncthreads();
    }

    #pragma unroll
    for (int rr = 0; rr < 4; rr++){
        const int i = w*4 + rr;
        float v0 = la[i][lane], v1 = la[i][lane+32];
        float bv; int bi;
        if (v1 > v0){ bv = v1; bi = lane + 32; } else { bv = v0; bi = lane; }
        #pragma unroll
        for (int off = 16; off > 0; off >>= 1){
            float ov = __shfl_xor_sync(0xffffffffu, bv, off);
            int   oi = __shfl_xor_sync(0xffffffffu, bi, off);
            if (ov > bv || (ov == bv && oi < bi)){ bv = ov; bi = oi; }
        }
        if (lane == 0){
            float conf = expf(bv);
            float at  = alive_t [b*Nn + i];
            float at1 = alive_t1[b*Nn + bi];
            float matched = (at > 0.5f && at1 > 0.5f && conf > 0.3f) ? 1.f : 0.f;
            out[b*Nn + i]           = (float)bi;   // perm
            out[Bb*Nn + b*Nn + i]   = matched;     // matched
        }
    }
}

// ================= launch =================
extern "C" void kernel_launch(void* const* d_in, const int* in_sizes, int n_in,
                              void* d_out, int out_size)
{
    const float* slots_t  = (const float*)d_in[0];
    const float* slots_t1 = (const float*)d_in[1];
    const float* alive_t  = (const float*)d_in[2];
    const float* alive_t1 = (const float*)d_in[3];
    const float* W1 = (const float*)d_in[4];
    const float* b1 = (const float*)d_in[5];
    const float* W2 = (const float*)d_in[6];
    const float* b2 = (const float*)d_in[7];
    const float* W3 = (const float*)d_in[8];
    const float* b3 = (const float*)d_in[9];
    float* out = (float*)d_out;

    cudaFuncSetAttribute(precompute_kernel, cudaFuncAttributeMaxDynamicSharedMemorySize, P_SMEM_BYTES);
    cudaFuncSetAttribute(score_kernel,      cudaFuncAttributeMaxDynamicSharedMemorySize, S_SMEM_BYTES);

    precompute_kernel<<<dim3(4, Bb), 512, P_SMEM_BYTES>>>(slots_t, slots_t1, W1, b1);
    score_kernel<<<dim3(Nn, Bb), 512, S_SMEM_BYTES>>>(slots_t, alive_t, alive_t1,
                                                      W1, W2, b2, W3, b3);
    sinkhorn_kernel<<<Bb, 512>>>(alive_t, alive_t1, out);
}